// round 11
// baseline (speedup 1.0000x reference)
#include <cuda_runtime.h>
#include <cuda_fp16.h>
#include <cstdint>
#include <math.h>

#define B_   2
#define SQ_  2048
#define SK_  2048
#define D_   1024
#define H_   16
#define HD_  64
#define MTOT (B_*SQ_)   // 4096

#define QSCALE (0.125f * 1.4426950408889634f)   // softmax scale * log2(e)

// ---------------------------------------------------------------------------
// fp16 scratch (allocation-free rule: __device__ globals)
// ---------------------------------------------------------------------------
__device__ __half g_xh  [MTOT*D_];        // x in fp16
__device__ __half g_eh  [MTOT*D_];        // encoder_output in fp16
__device__ __half g_Wqh [H_*HD_*D_];      // [n][k] fp16 (n = h*64+e)
__device__ __half g_Wkvh[2*H_*HD_*D_];    // rows 0..1023 = Wk, 1024..2047 = Wv
__device__ __half g_Woh [D_*D_];          // [n][k] fp16
__device__ __half g_Q   [B_*H_*SQ_*HD_];  // [B,H,SQ,HD], pre-scaled by QSCALE
__device__ __half g_K   [B_*H_*SK_*HD_];
__device__ __half g_V   [B_*H_*SK_*HD_];
__device__ __half g_C   [B_*SQ_*D_];      // concat attention out [B*SQ, D]

// ---------------------------------------------------------------------------
// helpers
// ---------------------------------------------------------------------------
__device__ __forceinline__ uint32_t smem_u32(const void* p) {
    uint32_t a;
    asm("{ .reg .u64 t; cvta.to.shared.u64 t, %1; cvt.u32.u64 %0, t; }"
        : "=r"(a) : "l"(p));
    return a;
}

__device__ __forceinline__ void mma_f16(float c[4], const uint32_t a[4],
                                        uint32_t b0, uint32_t b1) {
    asm volatile(
        "mma.sync.aligned.m16n8k16.row.col.f32.f16.f16.f32 "
        "{%0,%1,%2,%3}, {%4,%5,%6,%7}, {%8,%9}, {%0,%1,%2,%3};"
        : "+f"(c[0]), "+f"(c[1]), "+f"(c[2]), "+f"(c[3])
        : "r"(a[0]), "r"(a[1]), "r"(a[2]), "r"(a[3]), "r"(b0), "r"(b1));
}

__device__ __forceinline__ void ldmatrix_x4(uint32_t& r0, uint32_t& r1,
                                            uint32_t& r2, uint32_t& r3,
                                            uint32_t addr) {
    asm volatile(
        "ldmatrix.sync.aligned.m8n8.x4.shared.b16 {%0,%1,%2,%3}, [%4];"
        : "=r"(r0), "=r"(r1), "=r"(r2), "=r"(r3) : "r"(addr));
}

__device__ __forceinline__ void ldmatrix_x4_trans(uint32_t& r0, uint32_t& r1,
                                                  uint32_t& r2, uint32_t& r3,
                                                  uint32_t addr) {
    asm volatile(
        "ldmatrix.sync.aligned.m8n8.x4.trans.shared.b16 {%0,%1,%2,%3}, [%4];"
        : "=r"(r0), "=r"(r1), "=r"(r2), "=r"(r3) : "r"(addr));
}

__device__ __forceinline__ void cp16(uint32_t dst, const void* src) {
    asm volatile("cp.async.ca.shared.global [%0], [%1], 16;\n"
                 :: "r"(dst), "l"(src));
}
__device__ __forceinline__ void cp_commit() {
    asm volatile("cp.async.commit_group;\n");
}
template<int N> __device__ __forceinline__ void cp_wait() {
    asm volatile("cp.async.wait_group %0;\n" :: "n"(N));
}

__device__ __forceinline__ float ex2(float x) {
    float r;
    asm("ex2.approx.f32 %0, %1;" : "=f"(r) : "f"(x));
    return r;
}

__device__ __forceinline__ uint32_t packh2(float a, float b) {
    __half2 h = __floats2half2_rn(a, b);
    return *reinterpret_cast<uint32_t*>(&h);
}

// ---------------------------------------------------------------------------
// prepass 1: f32 -> fp16 elementwise, two tensors in one launch (grid.y)
// ---------------------------------------------------------------------------
__global__ __launch_bounds__(256)
void cvt_f2h2(const float* __restrict__ in0, __half* __restrict__ out0,
              const float* __restrict__ in1, __half* __restrict__ out1) {
    const float* in  = blockIdx.y ? in1  : in0;
    __half*      out = blockIdx.y ? out1 : out0;
    const int i = blockIdx.x * 256 + threadIdx.x;
    float4 v = ((const float4*)in)[i];
    uint2 u;
    u.x = packh2(v.x, v.y);
    u.y = packh2(v.z, v.w);
    ((uint2*)out)[i] = u;
}

// ---------------------------------------------------------------------------
// prepass 2a: fused QKV weight transpose+convert. Each head slab is
// f32 [D_,HD_] -> fp16 [HD_,D_]. z = w*16+h selects weight & head.
// ---------------------------------------------------------------------------
__global__ __launch_bounds__(256)
void tr_cvt3(const float* __restrict__ A0, __half* __restrict__ B0,
             const float* __restrict__ A1, __half* __restrict__ B1,
             const float* __restrict__ A2, __half* __restrict__ B2) {
    __shared__ float tile[32][33];
    const int w = blockIdx.z >> 4, h = blockIdx.z & 15;
    const float* in  = (w == 0 ? A0 : (w == 1 ? A1 : A2)) + (size_t)h * D_ * HD_;
    __half*      out = (w == 0 ? B0 : (w == 1 ? B1 : B2)) + (size_t)h * D_ * HD_;
    const int c0 = blockIdx.x * 32, r0 = blockIdx.y * 32;
    const int tx = threadIdx.x & 31, ty = threadIdx.x >> 5;
    #pragma unroll
    for (int i = 0; i < 32; i += 8)
        tile[ty + i][tx] = in[(size_t)(r0 + ty + i) * HD_ + c0 + tx];
    __syncthreads();
    #pragma unroll
    for (int i = 0; i < 32; i += 8)
        out[(size_t)(c0 + ty + i) * D_ + r0 + tx] =
            __float2half_rn(tile[tx][ty + i]);
}

// ---------------------------------------------------------------------------
// prepass 2b: generic transpose+convert (used for Wo). f32 [R,C] -> fp16 [C,R].
// ---------------------------------------------------------------------------
__global__ __launch_bounds__(256)
void tr_cvt(const float* __restrict__ in, __half* __restrict__ out,
            int R, int C) {
    __shared__ float tile[32][33];
    const int c0 = blockIdx.x * 32, r0 = blockIdx.y * 32;
    const int tx = threadIdx.x & 31, ty = threadIdx.x >> 5;
    #pragma unroll
    for (int i = 0; i < 32; i += 8)
        tile[ty + i][tx] = in[(size_t)(r0 + ty + i) * C + c0 + tx];
    __syncthreads();
    #pragma unroll
    for (int i = 0; i < 32; i += 8)
        out[(size_t)(c0 + ty + i) * R + r0 + tx] =
            __float2half_rn(tile[tx][ty + i]);
}

// ---------------------------------------------------------------------------
// fp16 mma GEMM v3: tile 128x128, 8 warps, BK=64, cp.async double-buffer,
// fragment loads via ldmatrix.x4 (A: 4/chunk, B: 32/chunk vs 160 scalar LDS).
// smem row = 64 halfs + pad = 36 words; ldmatrix row stride 144B -> banks
// r*4 mod 32, conflict-free.
// EPI 0 (headed half out): bx<8 -> out0/bias0 else out1/bias1, col (bx&7)*128.
// EPI 1 (flat f32): out0[m*D + bx*128+nl].
// ---------------------------------------------------------------------------
#define RSW 36                       // words per smem row
#define BUFW (128 * RSW)             // words per operand buffer (4608)
#define G2_SMEM (4 * BUFW * 4)       // 73,728 B

template<int EPI>
__global__ __launch_bounds__(256)
void gemm2(const __half* __restrict__ A, const __half* __restrict__ Wh,
           const float* __restrict__ bias0, const float* __restrict__ bias1,
           void* __restrict__ out0, void* __restrict__ out1, float scale)
{
    extern __shared__ uint32_t sm2[];
    const int t    = threadIdx.x;
    const int lane = t & 31, wid = t >> 5;
    const int gid  = lane >> 2, tid4 = lane & 3;
    const int w16  = wid * 16;
    const int bx   = blockIdx.x;
    const int m0   = blockIdx.y * 128;

    const __half* Wb = Wh + (size_t)bx * 128 * D_;
    const uint32_t smb = smem_u32(sm2);

    // ldmatrix lane->address offsets (bytes), fixed per lane:
    // q = matrix index (lane>>3), r = row within matrix (lane&7)
    const int q = lane >> 3, r = lane & 7;
    const uint32_t a_off = (uint32_t)((w16 + (q & 1) * 8 + r) * RSW + (q >> 1) * 4) * 4;
    const uint32_t b_off = (uint32_t)(((q >> 1) * 8 + r) * RSW + (q & 1) * 4) * 4;

    auto stage = [&](int kc) {
        const uint32_t ab = smb + (uint32_t)(kc & 1) * (2 * BUFW * 4);
        const uint32_t wb = ab + BUFW * 4;
        const int k0 = kc * 64;
        #pragma unroll
        for (int it = 0; it < 4; it++) {
            const int id  = t + it * 256;            // 0..1023
            const int row = id >> 3, ch = id & 7;    // 128 rows x 8 16B-chunks
            const uint32_t off = (uint32_t)(row * RSW + ch * 4) * 4;
            cp16(ab + off, A  + (size_t)(m0 + row) * D_ + k0 + ch * 8);
            cp16(wb + off, Wb + (size_t)row        * D_ + k0 + ch * 8);
        }
    };

    float c[16][4];
    #pragma unroll
    for (int j = 0; j < 16; j++)
        #pragma unroll
        for (int i = 0; i < 4; i++) c[j][i] = 0.f;

    stage(0); cp_commit();

    for (int kc = 0; kc < 16; kc++) {
        if (kc + 1 < 16) { stage(kc + 1); cp_commit(); cp_wait<1>(); }
        else             { cp_wait<0>(); }
        __syncthreads();

        const uint32_t aA = smb + (uint32_t)(kc & 1) * (2 * BUFW * 4) + a_off;
        const uint32_t bA = smb + (uint32_t)(kc & 1) * (2 * BUFW * 4) + BUFW * 4 + b_off;
        #pragma unroll
        for (int ks = 0; ks < 4; ks++) {
            uint32_t a[4];
            ldmatrix_x4(a[0], a[1], a[2], a[3], aA + ks * 32);
            #pragma unroll
            for (int jp = 0; jp < 8; jp++) {
                uint32_t b0, b1, b2, b3;
                ldmatrix_x4(b0, b1, b2, b3,
                            bA + (uint32_t)jp * (16 * RSW * 4) + ks * 32);
                mma_f16(c[2 * jp    ], a, b0, b1);
                mma_f16(c[2 * jp + 1], a, b2, b3);
            }
        }
        __syncthreads();
    }

    // Epilogue
    if (EPI == 0) {
        __half* outH    = (bx < 8) ? (__half*)out0 : (__half*)out1;
        const float* bs = (bx < 8) ? bias0 : bias1;
        const int nb    = (bx & 7) * 128;
        #pragma unroll
        for (int hh = 0; hh < 2; hh++) {
            const int m  = m0 + w16 + gid + hh * 8;
            const int bI = m >> 11, s = m & 2047;
            #pragma unroll
            for (int j = 0; j < 16; j++) {
                const int nf = nb + j * 8 + tid4 * 2;
                const float v0 = c[j][hh * 2 + 0] + bs[nf];
                const float v1 = c[j][hh * 2 + 1] + bs[nf + 1];
                const int head = nf >> 6, nl = nf & 63;
                *(uint32_t*)&outH[(((size_t)(bI * H_ + head)) * SQ_ + s) * HD_ + nl] =
                    packh2(v0 * scale, v1 * scale);
            }
        }
    } else {
        float* out = (float*)out0;
        #pragma unroll
        for (int hh = 0; hh < 2; hh++) {
            const int m = m0 + w16 + gid + hh * 8;
            #pragma unroll
            for (int j = 0; j < 16; j++) {
                const int nf = bx * 128 + j * 8 + tid4 * 2;
                const float v0 = c[j][hh * 2 + 0] + bias0[nf];
                const float v1 = c[j][hh * 2 + 1] + bias0[nf + 1];
                *(float2*)&out[(size_t)m * D_ + nf] = make_float2(v0, v1);
            }
        }
    }
}

// ---------------------------------------------------------------------------
// Flash attention, fp16 mma. Block = (b,h,128 q rows), 8 warps.
// K fragments now via ldmatrix.x4 (16/chunk vs 64 scalar LDS).
// ---------------------------------------------------------------------------
__global__ __launch_bounds__(256)
void flash_h()
{
    __shared__ uint32_t pool[9216];   // 36,864 B

    const int t    = threadIdx.x;
    const int lane = t & 31, wid = t >> 5;
    const int gid  = lane >> 2, tid4 = lane & 3;
    const int w16  = wid * 16;

    const int qt = blockIdx.x;
    const int h  = blockIdx.y;
    const int b  = blockIdx.z;

    const size_t qbase  = (((size_t)b * H_ + h) * SQ_ + qt * 128) * HD_;
    const size_t kvbase = (((size_t)b * H_ + h) * SK_) * HD_;

    const uint32_t pb = smem_u32(pool);

    // ldmatrix lane-offset for K fragments (same formula as gemm B, RSW=36)
    const int q = lane >> 3, r = lane & 7;
    const uint32_t kb_off = (uint32_t)(((q >> 1) * 8 + r) * 36 + (q & 1) * 4) * 4;

    #pragma unroll
    for (int it = 0; it < 4; it++) {
        const int id  = t + it * 256;
        const int row = id >> 3, c8 = (id & 7) * 8;
        cp16(pb + (uint32_t)(row * 36 + (id & 7) * 4) * 4,
             g_Q + qbase + (size_t)row * HD_ + c8);
    }
    cp_commit(); cp_wait<0>();
    __syncthreads();

    uint32_t aQ[4][4];
    #pragma unroll
    for (int ks = 0; ks < 4; ks++) {
        aQ[ks][0] = pool[(w16 + gid    ) * 36 + ks * 8 + tid4    ];
        aQ[ks][1] = pool[(w16 + gid + 8) * 36 + ks * 8 + tid4    ];
        aQ[ks][2] = pool[(w16 + gid    ) * 36 + ks * 8 + tid4 + 4];
        aQ[ks][3] = pool[(w16 + gid + 8) * 36 + ks * 8 + tid4 + 4];
    }
    __syncthreads();

    float cO[8][4];
    #pragma unroll
    for (int j = 0; j < 8; j++)
        #pragma unroll
        for (int i = 0; i < 4; i++) cO[j][i] = 0.f;
    float m0 = -1e30f, m1 = -1e30f, l0 = 0.f, l1 = 0.f;

    auto stageKV = [&](int buf, int c0) {
        #pragma unroll
        for (int it = 0; it < 2; it++) {
            const int id  = t + it * 256;
            const int row = id >> 3, c8 = (id & 7) * 8;
            const size_t go = kvbase + (size_t)(c0 + row) * HD_ + c8;
            cp16(pb + (uint32_t)(       buf * 2304 + row * 36 + (id & 7) * 4) * 4,
                 g_K + go);
            cp16(pb + (uint32_t)(4608 + buf * 2304 + row * 36 + (id & 7) * 4) * 4,
                 g_V + go);
        }
    };

    stageKV(0, 0);
    cp_commit();

    for (int cc = 0; cc < 32; cc++) {
        if (cc + 1 < 32) { stageKV((cc + 1) & 1, (cc + 1) * 64); cp_commit(); cp_wait<1>(); }
        else             { cp_wait<0>(); }
        __syncthreads();

        const uint32_t kA  = pb + (uint32_t)((cc & 1) * 2304) * 4 + kb_off;
        const uint32_t vsb = pb + (uint32_t)(4608 + (cc & 1) * 2304) * 4;

        float cS[8][4];
        #pragma unroll
        for (int j = 0; j < 8; j++)
            #pragma unroll
            for (int i = 0; i < 4; i++) cS[j][i] = 0.f;

        #pragma unroll
        for (int ks = 0; ks < 4; ks++) {
            #pragma unroll
            for (int jp = 0; jp < 4; jp++) {
                uint32_t b0, b1, b2, b3;
                ldmatrix_x4(b0, b1, b2, b3,
                            kA + (uint32_t)jp * (16 * 36 * 4) + ks * 32);
                mma_f16(cS[2 * jp    ], aQ[ks], b0, b1);
                mma_f16(cS[2 * jp + 1], aQ[ks], b2, b3);
            }
        }

        float mx0 = -1e30f, mx1 = -1e30f;
        #pragma unroll
        for (int j = 0; j < 8; j++) {
            mx0 = fmaxf(mx0, fmaxf(cS[j][0], cS[j][1]));
            mx1 = fmaxf(mx1, fmaxf(cS[j][2], cS[j][3]));
        }
        mx0 = fmaxf(mx0, __shfl_xor_sync(0xffffffffu, mx0, 1));
        mx0 = fmaxf(mx0, __shfl_xor_sync(0xffffffffu, mx0, 2));
        mx1 = fmaxf(mx1, __shfl_xor_sync(0xffffffffu, mx1, 1));
        mx1 = fmaxf(mx1, __shfl_xor_sync(0xffffffffu, mx1, 2));
        const float nm0 = fmaxf(m0, mx0), nm1 = fmaxf(m1, mx1);
        const float f0 = ex2(m0 - nm0), f1 = ex2(m1 - nm1);
        m0 = nm0; m1 = nm1;

        float s0 = 0.f, s1 = 0.f;
        uint32_t ph[8][2];
        #pragma unroll
        for (int j = 0; j < 8; j++) {
            const float p0 = ex2(cS[j][0] - m0);
            const float p1 = ex2(cS[j][1] - m0);
            const float p2 = ex2(cS[j][2] - m1);
            const float p3 = ex2(cS[j][3] - m1);
            s0 += p0 + p1;  s1 += p2 + p3;
            ph[j][0] = packh2(p0, p1);
            ph[j][1] = packh2(p2, p3);
        }
        s0 += __shfl_xor_sync(0xffffffffu, s0, 1);
        s0 += __shfl_xor_sync(0xffffffffu, s0, 2);
        s1 += __shfl_xor_sync(0xffffffffu, s1, 1);
        s1 += __shfl_xor_sync(0xffffffffu, s1, 2);
        l0 = l0 * f0 + s0;
        l1 = l1 * f1 + s1;

        #pragma unroll
        for (int j = 0; j < 8; j++) {
            cO[j][0] *= f0; cO[j][1] *= f0;
            cO[j][2] *= f1; cO[j][3] *= f1;
        }

        #pragma unroll
        for (int tk = 0; tk < 4; tk++) {
            uint32_t aP[4] = { ph[2*tk][0], ph[2*tk][1],
                               ph[2*tk+1][0], ph[2*tk+1][1] };
            #pragma unroll
            for (int jp = 0; jp < 4; jp++) {
                const int vrow = tk * 16 + (lane & 15);
                const int vcol = (lane >> 4) * 8 + jp * 16;
                uint32_t addr = vsb + (uint32_t)(vrow * 72 + vcol) * 2u;
                uint32_t r0, r1, r2, r3;
                ldmatrix_x4_trans(r0, r1, r2, r3, addr);
                mma_f16(cO[2*jp    ], aP, r0, r1);
                mma_f16(cO[2*jp + 1], aP, r2, r3);
            }
        }
        __syncthreads();
    }

    const float inv0 = 1.f / l0;
    const float inv1 = 1.f / l1;
    const int qrow = qt * 128 + w16 + gid;
    __half* op0 = g_C + ((size_t)(b * SQ_ + qrow)) * D_ + h * HD_;
    __half* op1 = op0 + (size_t)8 * D_;
    #pragma unroll
    for (int j = 0; j < 8; j++) {
        const int nl = j * 8 + tid4 * 2;
        *(uint32_t*)&op0[nl] = packh2(cO[j][0] * inv0, cO[j][1] * inv0);
        *(uint32_t*)&op1[nl] = packh2(cO[j][2] * inv1, cO[j][3] * inv1);
    }
}

// ---------------------------------------------------------------------------
extern "C" void kernel_launch(void* const* d_in, const int* in_sizes, int n_in,
                              void* d_out, int out_size)
{
    const float* x   = (const float*)d_in[0];
    const float* enc = (const float*)d_in[1];
    const float* Wq  = (const float*)d_in[2];
    const float* bq  = (const float*)d_in[3];
    const float* Wk  = (const float*)d_in[4];
    const float* bk  = (const float*)d_in[5];
    const float* Wv  = (const float*)d_in[6];
    const float* bv  = (const float*)d_in[7];
    const float* Wo  = (const float*)d_in[8];
    const float* bo  = (const float*)d_in[9];

    __half *xh, *eh, *Wqh, *Wkvh, *Woh, *Qp, *Kp, *Vp, *Cp;
    cudaGetSymbolAddress((void**)&xh,   g_xh);
    cudaGetSymbolAddress((void**)&eh,   g_eh);
    cudaGetSymbolAddress((void**)&Wqh,  g_Wqh);
    cudaGetSymbolAddress((void**)&Wkvh, g_Wkvh);
    cudaGetSymbolAddress((void**)&Woh,  g_Woh);
    cudaGetSymbolAddress((void**)&Qp,   g_Q);
    cudaGetSymbolAddress((void**)&Kp,   g_K);
    cudaGetSymbolAddress((void**)&Vp,   g_V);
    cudaGetSymbolAddress((void**)&Cp,   g_C);

    // Prepass (fused): activations, QKV weights, Wo
    cvt_f2h2<<<dim3((MTOT*D_/4)/256, 2), 256>>>(x, xh, enc, eh);
    tr_cvt3<<<dim3(HD_/32, D_/32, 3*H_), 256>>>(Wq, Wqh,
                                                Wk, Wkvh,
                                                Wv, Wkvh + (size_t)D_*D_);
    tr_cvt<<<dim3(D_/32, D_/32), 256>>>(Wo, Woh, D_, D_);

    cudaFuncSetAttribute(gemm2<0>, cudaFuncAttributeMaxDynamicSharedMemorySize,
                         G2_SMEM);
    cudaFuncSetAttribute(gemm2<1>, cudaFuncAttributeMaxDynamicSharedMemorySize,
                         G2_SMEM);

    // Q projection: N=1024 (8 tiles)
    gemm2<0><<<dim3(8, MTOT/128), 256, G2_SMEM>>>(xh, Wqh, bq, bq, Qp, Qp, QSCALE);
    // K+V fused: N=2048 (16 tiles; bx<8 -> K, bx>=8 -> V)
    gemm2<0><<<dim3(16, MTOT/128), 256, G2_SMEM>>>(eh, Wkvh, bk, bv, Kp, Vp, 1.f);

    flash_h<<<dim3(SQ_/128, H_, B_), 256>>>();

    // Output projection: f32 into d_out
    gemm2<1><<<dim3(8, MTOT/128), 256, G2_SMEM>>>(Cp, Woh, bo, bo, d_out, d_out, 1.f);
}

// round 12
// speedup vs baseline: 1.3902x; 1.3902x over previous
#include <cuda_runtime.h>
#include <cuda_fp16.h>
#include <cstdint>
#include <math.h>

#define B_   2
#define SQ_  2048
#define SK_  2048
#define D_   1024
#define H_   16
#define HD_  64
#define MTOT (B_*SQ_)   // 4096

#define QSCALE (0.125f * 1.4426950408889634f)   // softmax scale * log2(e)

// ---------------------------------------------------------------------------
// fp16 scratch (allocation-free rule: __device__ globals)
// ---------------------------------------------------------------------------
__device__ __half g_xh  [MTOT*D_];        // x in fp16
__device__ __half g_eh  [MTOT*D_];        // encoder_output in fp16
__device__ __half g_Wqh [H_*HD_*D_];      // [n][k] fp16 (n = h*64+e)
__device__ __half g_Wkvh[2*H_*HD_*D_];    // rows 0..1023 = Wk, 1024..2047 = Wv
__device__ __half g_Woh [D_*D_];          // [n][k] fp16
__device__ __half g_Q   [B_*H_*SQ_*HD_];  // [B,H,SQ,HD], pre-scaled by QSCALE
__device__ __half g_K   [B_*H_*SK_*HD_];
__device__ __half g_V   [B_*H_*SK_*HD_];
__device__ __half g_C   [B_*SQ_*D_];      // concat attention out [B*SQ, D]

// ---------------------------------------------------------------------------
// helpers
// ---------------------------------------------------------------------------
__device__ __forceinline__ uint32_t smem_u32(const void* p) {
    uint32_t a;
    asm("{ .reg .u64 t; cvta.to.shared.u64 t, %1; cvt.u32.u64 %0, t; }"
        : "=r"(a) : "l"(p));
    return a;
}

__device__ __forceinline__ void mma_f16(float c[4], const uint32_t a[4],
                                        uint32_t b0, uint32_t b1) {
    asm volatile(
        "mma.sync.aligned.m16n8k16.row.col.f32.f16.f16.f32 "
        "{%0,%1,%2,%3}, {%4,%5,%6,%7}, {%8,%9}, {%0,%1,%2,%3};"
        : "+f"(c[0]), "+f"(c[1]), "+f"(c[2]), "+f"(c[3])
        : "r"(a[0]), "r"(a[1]), "r"(a[2]), "r"(a[3]), "r"(b0), "r"(b1));
}

__device__ __forceinline__ void ldmatrix_x4_trans(uint32_t& r0, uint32_t& r1,
                                                  uint32_t& r2, uint32_t& r3,
                                                  uint32_t addr) {
    asm volatile(
        "ldmatrix.sync.aligned.m8n8.x4.trans.shared.b16 {%0,%1,%2,%3}, [%4];"
        : "=r"(r0), "=r"(r1), "=r"(r2), "=r"(r3) : "r"(addr));
}

__device__ __forceinline__ void cp16(uint32_t dst, const void* src) {
    asm volatile("cp.async.ca.shared.global [%0], [%1], 16;\n"
                 :: "r"(dst), "l"(src));
}
__device__ __forceinline__ void cp_commit() {
    asm volatile("cp.async.commit_group;\n");
}
template<int N> __device__ __forceinline__ void cp_wait() {
    asm volatile("cp.async.wait_group %0;\n" :: "n"(N));
}

__device__ __forceinline__ float ex2(float x) {
    float r;
    asm("ex2.approx.f32 %0, %1;" : "=f"(r) : "f"(x));
    return r;
}

__device__ __forceinline__ uint32_t packh2(float a, float b) {
    __half2 h = __floats2half2_rn(a, b);
    return *reinterpret_cast<uint32_t*>(&h);
}

// ---------------------------------------------------------------------------
// prepass 1: f32 -> fp16 elementwise, two tensors in one launch (grid.y)
// ---------------------------------------------------------------------------
__global__ __launch_bounds__(256)
void cvt_f2h2(const float* __restrict__ in0, __half* __restrict__ out0,
              const float* __restrict__ in1, __half* __restrict__ out1) {
    const float* in  = blockIdx.y ? in1  : in0;
    __half*      out = blockIdx.y ? out1 : out0;
    const int i = blockIdx.x * 256 + threadIdx.x;
    float4 v = ((const float4*)in)[i];
    uint2 u;
    u.x = packh2(v.x, v.y);
    u.y = packh2(v.z, v.w);
    ((uint2*)out)[i] = u;
}

// ---------------------------------------------------------------------------
// prepass 2a: fused QKV weight transpose+convert. Each head slab is
// f32 [D_,HD_] -> fp16 [HD_,D_]. z = w*16+h selects weight & head.
// ---------------------------------------------------------------------------
__global__ __launch_bounds__(256)
void tr_cvt3(const float* __restrict__ A0, __half* __restrict__ B0,
             const float* __restrict__ A1, __half* __restrict__ B1,
             const float* __restrict__ A2, __half* __restrict__ B2) {
    __shared__ float tile[32][33];
    const int w = blockIdx.z >> 4, h = blockIdx.z & 15;
    const float* in  = (w == 0 ? A0 : (w == 1 ? A1 : A2)) + (size_t)h * D_ * HD_;
    __half*      out = (w == 0 ? B0 : (w == 1 ? B1 : B2)) + (size_t)h * D_ * HD_;
    const int c0 = blockIdx.x * 32, r0 = blockIdx.y * 32;
    const int tx = threadIdx.x & 31, ty = threadIdx.x >> 5;
    #pragma unroll
    for (int i = 0; i < 32; i += 8)
        tile[ty + i][tx] = in[(size_t)(r0 + ty + i) * HD_ + c0 + tx];
    __syncthreads();
    #pragma unroll
    for (int i = 0; i < 32; i += 8)
        out[(size_t)(c0 + ty + i) * D_ + r0 + tx] =
            __float2half_rn(tile[tx][ty + i]);
}

// ---------------------------------------------------------------------------
// prepass 2b: generic transpose+convert (Wo). f32 [R,C] -> fp16 [C,R].
// ---------------------------------------------------------------------------
__global__ __launch_bounds__(256)
void tr_cvt(const float* __restrict__ in, __half* __restrict__ out,
            int R, int C) {
    __shared__ float tile[32][33];
    const int c0 = blockIdx.x * 32, r0 = blockIdx.y * 32;
    const int tx = threadIdx.x & 31, ty = threadIdx.x >> 5;
    #pragma unroll
    for (int i = 0; i < 32; i += 8)
        tile[ty + i][tx] = in[(size_t)(r0 + ty + i) * C + c0 + tx];
    __syncthreads();
    #pragma unroll
    for (int i = 0; i < 32; i += 8)
        out[(size_t)(c0 + ty + i) * R + r0 + tx] =
            __float2half_rn(tile[tx][ty + i]);
}

// ---------------------------------------------------------------------------
// fp16 mma GEMM: tile 128x128, 8 warps, BK=64, scalar-LDS fragment loads
// (proven fastest: deep reorderable load stream hides smem latency),
// 3-stage cp.async pipeline -> ONE __syncthreads per K-chunk.
// EPI 0 (merged QKV): bx<8 -> Q(out0,bias0,scale), 8..15 -> K(out1,bias1),
//   16..23 -> V(out2,bias2). A = bx<8 ? A0 : A1. W selected per range.
// EPI 1 (flat f32): out0[m*D + bx*128+nl] = acc + bias0.
// ---------------------------------------------------------------------------
#define RSW 36                       // words per smem row
#define BUFW (128 * RSW)             // words per operand buffer (4608)
#define G2_SMEM (6 * BUFW * 4)       // 3 stages x (A|W) = 110,592 B

template<int EPI>
__global__ __launch_bounds__(256)
void gemm2(const __half* __restrict__ A0, const __half* __restrict__ A1,
           const __half* __restrict__ Wq, const __half* __restrict__ Wkv,
           const float* __restrict__ bias0, const float* __restrict__ bias1,
           const float* __restrict__ bias2,
           void* __restrict__ out0, void* __restrict__ out1,
           void* __restrict__ out2, float scale0)
{
    extern __shared__ uint32_t sm2[];
    const int t    = threadIdx.x;
    const int lane = t & 31, wid = t >> 5;
    const int gid  = lane >> 2, tid4 = lane & 3;
    const int w16  = wid * 16;
    const int bx   = blockIdx.x;
    const int m0   = blockIdx.y * 128;

    const __half* A;
    const __half* Wb;
    if (EPI == 0) {
        A  = (bx < 8) ? A0 : A1;
        Wb = (bx < 8) ? Wq + (size_t)bx * 128 * D_
                      : Wkv + (size_t)(bx - 8) * 128 * D_;
    } else {
        A  = A0;
        Wb = Wq + (size_t)bx * 128 * D_;
    }
    const uint32_t smb = smem_u32(sm2);

    auto stage = [&](int kc) {
        const uint32_t ab = smb + (uint32_t)(kc % 3) * (2 * BUFW * 4);
        const uint32_t wb = ab + BUFW * 4;
        const int k0 = kc * 64;
        #pragma unroll
        for (int it = 0; it < 4; it++) {
            const int id  = t + it * 256;            // 0..1023
            const int row = id >> 3, ch = id & 7;    // 128 rows x 8 16B-chunks
            const uint32_t off = (uint32_t)(row * RSW + ch * 4) * 4;
            cp16(ab + off, A  + (size_t)(m0 + row) * D_ + k0 + ch * 8);
            cp16(wb + off, Wb + (size_t)row        * D_ + k0 + ch * 8);
        }
    };

    float c[16][4];
    #pragma unroll
    for (int j = 0; j < 16; j++)
        #pragma unroll
        for (int i = 0; i < 4; i++) c[j][i] = 0.f;

    stage(0); cp_commit();
    stage(1); cp_commit();

    for (int kc = 0; kc < 16; kc++) {
        if (kc < 15) cp_wait<1>(); else cp_wait<0>();
        __syncthreads();                       // buf kc ready for ALL threads;
                                               // also: iter kc-1 reads done
        if (kc + 2 < 16) { stage(kc + 2); cp_commit(); }

        const uint32_t* Ab = sm2 + (kc % 3) * 2 * BUFW;
        const uint32_t* Bb = Ab + BUFW;
        #pragma unroll
        for (int ks = 0; ks < 4; ks++) {
            uint32_t a[4];
            a[0] = Ab[(w16 + gid    ) * RSW + ks * 8 + tid4    ];
            a[1] = Ab[(w16 + gid + 8) * RSW + ks * 8 + tid4    ];
            a[2] = Ab[(w16 + gid    ) * RSW + ks * 8 + tid4 + 4];
            a[3] = Ab[(w16 + gid + 8) * RSW + ks * 8 + tid4 + 4];
            #pragma unroll
            for (int j = 0; j < 16; j++) {
                uint32_t b0 = Bb[(j * 8 + gid) * RSW + ks * 8 + tid4    ];
                uint32_t b1 = Bb[(j * 8 + gid) * RSW + ks * 8 + tid4 + 4];
                mma_f16(c[j], a, b0, b1);
            }
        }
    }

    // Epilogue
    if (EPI == 0) {
        __half* outH;
        const float* bs;
        float scale = 1.f;
        int nb;
        if (bx < 8)       { outH = (__half*)out0; bs = bias0; nb = bx * 128;        scale = scale0; }
        else if (bx < 16) { outH = (__half*)out1; bs = bias1; nb = (bx - 8) * 128;  }
        else              { outH = (__half*)out2; bs = bias2; nb = (bx - 16) * 128; }
        #pragma unroll
        for (int hh = 0; hh < 2; hh++) {
            const int m  = m0 + w16 + gid + hh * 8;
            const int bI = m >> 11, s = m & 2047;
            #pragma unroll
            for (int j = 0; j < 16; j++) {
                const int nf = nb + j * 8 + tid4 * 2;
                const float v0 = c[j][hh * 2 + 0] + bs[nf];
                const float v1 = c[j][hh * 2 + 1] + bs[nf + 1];
                const int head = nf >> 6, nl = nf & 63;
                *(uint32_t*)&outH[(((size_t)(bI * H_ + head)) * SQ_ + s) * HD_ + nl] =
                    packh2(v0 * scale, v1 * scale);
            }
        }
    } else {
        float* out = (float*)out0;
        #pragma unroll
        for (int hh = 0; hh < 2; hh++) {
            const int m = m0 + w16 + gid + hh * 8;
            #pragma unroll
            for (int j = 0; j < 16; j++) {
                const int nf = bx * 128 + j * 8 + tid4 * 2;
                const float v0 = c[j][hh * 2 + 0] + bias0[nf];
                const float v1 = c[j][hh * 2 + 1] + bias0[nf + 1];
                *(float2*)&out[(size_t)m * D_ + nf] = make_float2(v0, v1);
            }
        }
    }
}

// ---------------------------------------------------------------------------
// Flash attention, fp16 mma (byte-identical to the 301us R10 version).
// Block = (b,h,128 q rows), 8 warps, scalar LDS K-frags, x4.trans V.
// ---------------------------------------------------------------------------
__global__ __launch_bounds__(256)
void flash_h()
{
    __shared__ uint32_t pool[9216];   // 36,864 B

    const int t    = threadIdx.x;
    const int lane = t & 31, wid = t >> 5;
    const int gid  = lane >> 2, tid4 = lane & 3;
    const int w16  = wid * 16;

    const int qt = blockIdx.x;
    const int h  = blockIdx.y;
    const int b  = blockIdx.z;

    const size_t qbase  = (((size_t)b * H_ + h) * SQ_ + qt * 128) * HD_;
    const size_t kvbase = (((size_t)b * H_ + h) * SK_) * HD_;

    const uint32_t pb = smem_u32(pool);

    #pragma unroll
    for (int it = 0; it < 4; it++) {
        const int id  = t + it * 256;
        const int row = id >> 3, c8 = (id & 7) * 8;
        cp16(pb + (uint32_t)(row * 36 + (id & 7) * 4) * 4,
             g_Q + qbase + (size_t)row * HD_ + c8);
    }
    cp_commit(); cp_wait<0>();
    __syncthreads();

    uint32_t aQ[4][4];
    #pragma unroll
    for (int ks = 0; ks < 4; ks++) {
        aQ[ks][0] = pool[(w16 + gid    ) * 36 + ks * 8 + tid4    ];
        aQ[ks][1] = pool[(w16 + gid + 8) * 36 + ks * 8 + tid4    ];
        aQ[ks][2] = pool[(w16 + gid    ) * 36 + ks * 8 + tid4 + 4];
        aQ[ks][3] = pool[(w16 + gid + 8) * 36 + ks * 8 + tid4 + 4];
    }
    __syncthreads();

    float cO[8][4];
    #pragma unroll
    for (int j = 0; j < 8; j++)
        #pragma unroll
        for (int i = 0; i < 4; i++) cO[j][i] = 0.f;
    float m0 = -1e30f, m1 = -1e30f, l0 = 0.f, l1 = 0.f;

    auto stageKV = [&](int buf, int c0) {
        #pragma unroll
        for (int it = 0; it < 2; it++) {
            const int id  = t + it * 256;
            const int row = id >> 3, c8 = (id & 7) * 8;
            const size_t go = kvbase + (size_t)(c0 + row) * HD_ + c8;
            cp16(pb + (uint32_t)(       buf * 2304 + row * 36 + (id & 7) * 4) * 4,
                 g_K + go);
            cp16(pb + (uint32_t)(4608 + buf * 2304 + row * 36 + (id & 7) * 4) * 4,
                 g_V + go);
        }
    };

    stageKV(0, 0);
    cp_commit();

    for (int cc = 0; cc < 32; cc++) {
        if (cc + 1 < 32) { stageKV((cc + 1) & 1, (cc + 1) * 64); cp_commit(); cp_wait<1>(); }
        else             { cp_wait<0>(); }
        __syncthreads();

        const uint32_t* Ks = pool + (cc & 1) * 2304;
        const uint32_t  vsb = pb + (uint32_t)(4608 + (cc & 1) * 2304) * 4;

        float cS[8][4];
        #pragma unroll
        for (int j = 0; j < 8; j++)
            #pragma unroll
            for (int i = 0; i < 4; i++) cS[j][i] = 0.f;

        #pragma unroll
        for (int ks = 0; ks < 4; ks++) {
            #pragma unroll
            for (int j = 0; j < 8; j++) {
                uint32_t b0 = Ks[(j * 8 + gid) * 36 + ks * 8 + tid4    ];
                uint32_t b1 = Ks[(j * 8 + gid) * 36 + ks * 8 + tid4 + 4];
                mma_f16(cS[j], aQ[ks], b0, b1);
            }
        }

        float mx0 = -1e30f, mx1 = -1e30f;
        #pragma unroll
        for (int j = 0; j < 8; j++) {
            mx0 = fmaxf(mx0, fmaxf(cS[j][0], cS[j][1]));
            mx1 = fmaxf(mx1, fmaxf(cS[j][2], cS[j][3]));
        }
        mx0 = fmaxf(mx0, __shfl_xor_sync(0xffffffffu, mx0, 1));
        mx0 = fmaxf(mx0, __shfl_xor_sync(0xffffffffu, mx0, 2));
        mx1 = fmaxf(mx1, __shfl_xor_sync(0xffffffffu, mx1, 1));
        mx1 = fmaxf(mx1, __shfl_xor_sync(0xffffffffu, mx1, 2));
        const float nm0 = fmaxf(m0, mx0), nm1 = fmaxf(m1, mx1);
        const float f0 = ex2(m0 - nm0), f1 = ex2(m1 - nm1);
        m0 = nm0; m1 = nm1;

        float s0 = 0.f, s1 = 0.f;
        uint32_t ph[8][2];
        #pragma unroll
        for (int j = 0; j < 8; j++) {
            const float p0 = ex2(cS[j][0] - m0);
            const float p1 = ex2(cS[j][1] - m0);
            const float p2 = ex2(cS[j][2] - m1);
            const float p3 = ex2(cS[j][3] - m1);
            s0 += p0 + p1;  s1 += p2 + p3;
            ph[j][0] = packh2(p0, p1);
            ph[j][1] = packh2(p2, p3);
        }
        s0 += __shfl_xor_sync(0xffffffffu, s0, 1);
        s0 += __shfl_xor_sync(0xffffffffu, s0, 2);
        s1 += __shfl_xor_sync(0xffffffffu, s1, 1);
        s1 += __shfl_xor_sync(0xffffffffu, s1, 2);
        l0 = l0 * f0 + s0;
        l1 = l1 * f1 + s1;

        #pragma unroll
        for (int j = 0; j < 8; j++) {
            cO[j][0] *= f0; cO[j][1] *= f0;
            cO[j][2] *= f1; cO[j][3] *= f1;
        }

        #pragma unroll
        for (int tk = 0; tk < 4; tk++) {
            uint32_t aP[4] = { ph[2*tk][0], ph[2*tk][1],
                               ph[2*tk+1][0], ph[2*tk+1][1] };
            #pragma unroll
            for (int jp = 0; jp < 4; jp++) {
                const int vrow = tk * 16 + (lane & 15);
                const int vcol = (lane >> 4) * 8 + jp * 16;
                uint32_t addr = vsb + (uint32_t)(vrow * 72 + vcol) * 2u;
                uint32_t r0, r1, r2, r3;
                ldmatrix_x4_trans(r0, r1, r2, r3, addr);
                mma_f16(cO[2*jp    ], aP, r0, r1);
                mma_f16(cO[2*jp + 1], aP, r2, r3);
            }
        }
        __syncthreads();
    }

    const float inv0 = 1.f / l0;
    const float inv1 = 1.f / l1;
    const int qrow = qt * 128 + w16 + gid;
    __half* op0 = g_C + ((size_t)(b * SQ_ + qrow)) * D_ + h * HD_;
    __half* op1 = op0 + (size_t)8 * D_;
    #pragma unroll
    for (int j = 0; j < 8; j++) {
        const int nl = j * 8 + tid4 * 2;
        *(uint32_t*)&op0[nl] = packh2(cO[j][0] * inv0, cO[j][1] * inv0);
        *(uint32_t*)&op1[nl] = packh2(cO[j][2] * inv1, cO[j][3] * inv1);
    }
}

// ---------------------------------------------------------------------------
extern "C" void kernel_launch(void* const* d_in, const int* in_sizes, int n_in,
                              void* d_out, int out_size)
{
    const float* x   = (const float*)d_in[0];
    const float* enc = (const float*)d_in[1];
    const float* Wq  = (const float*)d_in[2];
    const float* bq  = (const float*)d_in[3];
    const float* Wk  = (const float*)d_in[4];
    const float* bk  = (const float*)d_in[5];
    const float* Wv  = (const float*)d_in[6];
    const float* bv  = (const float*)d_in[7];
    const float* Wo  = (const float*)d_in[8];
    const float* bo  = (const float*)d_in[9];

    __half *xh, *eh, *Wqh, *Wkvh, *Woh, *Qp, *Kp, *Vp, *Cp;
    cudaGetSymbolAddress((void**)&xh,   g_xh);
    cudaGetSymbolAddress((void**)&eh,   g_eh);
    cudaGetSymbolAddress((void**)&Wqh,  g_Wqh);
    cudaGetSymbolAddress((void**)&Wkvh, g_Wkvh);
    cudaGetSymbolAddress((void**)&Woh,  g_Woh);
    cudaGetSymbolAddress((void**)&Qp,   g_Q);
    cudaGetSymbolAddress((void**)&Kp,   g_K);
    cudaGetSymbolAddress((void**)&Vp,   g_V);
    cudaGetSymbolAddress((void**)&Cp,   g_C);

    // Prepass (fused): activations, QKV weights, Wo
    cvt_f2h2<<<dim3((MTOT*D_/4)/256, 2), 256>>>(x, xh, enc, eh);
    tr_cvt3<<<dim3(HD_/32, D_/32, 3*H_), 256>>>(Wq, Wqh,
                                                Wk, Wkvh,
                                                Wv, Wkvh + (size_t)D_*D_);
    tr_cvt<<<dim3(D_/32, D_/32), 256>>>(Wo, Woh, D_, D_);

    cudaFuncSetAttribute(gemm2<0>, cudaFuncAttributeMaxDynamicSharedMemorySize,
                         G2_SMEM);
    cudaFuncSetAttribute(gemm2<1>, cudaFuncAttributeMaxDynamicSharedMemorySize,
                         G2_SMEM);

    // Merged Q+K+V projections: 24 N-tiles (Q:0-7, K:8-15, V:16-23)
    gemm2<0><<<dim3(24, MTOT/128), 256, G2_SMEM>>>(
        xh, eh, Wqh, Wkvh, bq, bk, bv, Qp, Kp, Vp, QSCALE);

    flash_h<<<dim3(SQ_/128, H_, B_), 256>>>();

    // Output projection: f32 into d_out
    gemm2<1><<<dim3(8, MTOT/128), 256, G2_SMEM>>>(
        Cp, Cp, Woh, Woh, bo, bo, bo, d_out, d_out, d_out, 1.f);
}

// round 16
// speedup vs baseline: 1.5334x; 1.1030x over previous
#include <cuda_runtime.h>
#include <cuda_fp16.h>
#include <cstdint>
#include <math.h>

#define B_   2
#define SQ_  2048
#define SK_  2048
#define D_   1024
#define H_   16
#define HD_  64
#define MTOT (B_*SQ_)   // 4096

#define QSCALE (0.125f * 1.4426950408889634f)   // softmax scale * log2(e)

// ---------------------------------------------------------------------------
// fp16 scratch (allocation-free rule: __device__ globals)
// ---------------------------------------------------------------------------
__device__ __half g_xh  [MTOT*D_];        // x in fp16
__device__ __half g_eh  [MTOT*D_];        // encoder_output in fp16
__device__ __half g_Wqh [H_*HD_*D_];      // [n][k] fp16 (n = h*64+e)
__device__ __half g_Wkvh[2*H_*HD_*D_];    // rows 0..1023 = Wk, 1024..2047 = Wv
__device__ __half g_Woh [D_*D_];          // [n][k] fp16
__device__ __half g_Q   [B_*H_*SQ_*HD_];  // [B,H,SQ,HD], pre-scaled by QSCALE
__device__ __half g_K   [B_*H_*SK_*HD_];
__device__ __half g_V   [B_*H_*SK_*HD_];
__device__ __half g_C   [B_*SQ_*D_];      // concat attention out [B*SQ, D]

// ---------------------------------------------------------------------------
// helpers
// ---------------------------------------------------------------------------
__device__ __forceinline__ uint32_t smem_u32(const void* p) {
    uint32_t a;
    asm("{ .reg .u64 t; cvta.to.shared.u64 t, %1; cvt.u32.u64 %0, t; }"
        : "=r"(a) : "l"(p));
    return a;
}

__device__ __forceinline__ void mma_f16(float c[4], const uint32_t a[4],
                                        uint32_t b0, uint32_t b1) {
    asm volatile(
        "mma.sync.aligned.m16n8k16.row.col.f32.f16.f16.f32 "
        "{%0,%1,%2,%3}, {%4,%5,%6,%7}, {%8,%9}, {%0,%1,%2,%3};"
        : "+f"(c[0]), "+f"(c[1]), "+f"(c[2]), "+f"(c[3])
        : "r"(a[0]), "r"(a[1]), "r"(a[2]), "r"(a[3]), "r"(b0), "r"(b1));
}

__device__ __forceinline__ void ldmatrix_x4_trans(uint32_t& r0, uint32_t& r1,
                                                  uint32_t& r2, uint32_t& r3,
                                                  uint32_t addr) {
    asm volatile(
        "ldmatrix.sync.aligned.m8n8.x4.trans.shared.b16 {%0,%1,%2,%3}, [%4];"
        : "=r"(r0), "=r"(r1), "=r"(r2), "=r"(r3) : "r"(addr));
}

__device__ __forceinline__ void cp16(uint32_t dst, const void* src) {
    asm volatile("cp.async.ca.shared.global [%0], [%1], 16;\n"
                 :: "r"(dst), "l"(src));
}
__device__ __forceinline__ void cp_commit() {
    asm volatile("cp.async.commit_group;\n");
}
template<int N> __device__ __forceinline__ void cp_wait() {
    asm volatile("cp.async.wait_group %0;\n" :: "n"(N));
}

__device__ __forceinline__ float ex2(float x) {
    float r;
    asm("ex2.approx.f32 %0, %1;" : "=f"(r) : "f"(x));
    return r;
}

__device__ __forceinline__ uint32_t packh2(float a, float b) {
    __half2 h = __floats2half2_rn(a, b);
    return *reinterpret_cast<uint32_t*>(&h);
}

// ---------------------------------------------------------------------------
// prepass 1: f32 -> fp16 elementwise, two tensors in one launch (grid.y)
// ---------------------------------------------------------------------------
__global__ __launch_bounds__(256)
void cvt_f2h2(const float* __restrict__ in0, __half* __restrict__ out0,
              const float* __restrict__ in1, __half* __restrict__ out1) {
    const float* in  = blockIdx.y ? in1  : in0;
    __half*      out = blockIdx.y ? out1 : out0;
    const int i = blockIdx.x * 256 + threadIdx.x;
    float4 v = ((const float4*)in)[i];
    uint2 u;
    u.x = packh2(v.x, v.y);
    u.y = packh2(v.z, v.w);
    ((uint2*)out)[i] = u;
}

// ---------------------------------------------------------------------------
// prepass 2a: fused QKV weight transpose+convert. Each head slab is
// f32 [D_,HD_] -> fp16 [HD_,D_]. z = w*16+h selects weight & head.
// ---------------------------------------------------------------------------
__global__ __launch_bounds__(256)
void tr_cvt3(const float* __restrict__ A0, __half* __restrict__ B0,
             const float* __restrict__ A1, __half* __restrict__ B1,
             const float* __restrict__ A2, __half* __restrict__ B2) {
    __shared__ float tile[32][33];
    const int w = blockIdx.z >> 4, h = blockIdx.z & 15;
    const float* in  = (w == 0 ? A0 : (w == 1 ? A1 : A2)) + (size_t)h * D_ * HD_;
    __half*      out = (w == 0 ? B0 : (w == 1 ? B1 : B2)) + (size_t)h * D_ * HD_;
    const int c0 = blockIdx.x * 32, r0 = blockIdx.y * 32;
    const int tx = threadIdx.x & 31, ty = threadIdx.x >> 5;
    #pragma unroll
    for (int i = 0; i < 32; i += 8)
        tile[ty + i][tx] = in[(size_t)(r0 + ty + i) * HD_ + c0 + tx];
    __syncthreads();
    #pragma unroll
    for (int i = 0; i < 32; i += 8)
        out[(size_t)(c0 + ty + i) * D_ + r0 + tx] =
            __float2half_rn(tile[tx][ty + i]);
}

// ---------------------------------------------------------------------------
// prepass 2b: generic transpose+convert (Wo). f32 [R,C] -> fp16 [C,R].
// ---------------------------------------------------------------------------
__global__ __launch_bounds__(256)
void tr_cvt(const float* __restrict__ in, __half* __restrict__ out,
            int R, int C) {
    __shared__ float tile[32][33];
    const int c0 = blockIdx.x * 32, r0 = blockIdx.y * 32;
    const int tx = threadIdx.x & 31, ty = threadIdx.x >> 5;
    #pragma unroll
    for (int i = 0; i < 32; i += 8)
        tile[ty + i][tx] = in[(size_t)(r0 + ty + i) * C + c0 + tx];
    __syncthreads();
    #pragma unroll
    for (int i = 0; i < 32; i += 8)
        out[(size_t)(c0 + ty + i) * R + r0 + tx] =
            __float2half_rn(tile[tx][ty + i]);
}

// ---------------------------------------------------------------------------
// fp16 mma GEMM: block tile 128x128, 8 warps in a 4(M) x 2(N) grid —
// warp tile 32x64. Per chunk: 32 A + 64 B frag-LDS (vs 144 for 16x128),
// same 64 HMMA; each B fragment feeds two mmas. Scalar LDS (proven vs
// ldmatrix), BK=64, 2-stage cp.async (proven vs 3-stage).
// EPI 0 (merged QKV): bx<8 -> Q(out0,bias0,scale0), 8..15 -> K, 16..23 -> V.
// EPI 1 (flat f32): out0[m*D + bx*128+nl] = acc + bias0.
// ---------------------------------------------------------------------------
#define RSW 36                       // words per smem row
#define BUFW (128 * RSW)             // words per operand buffer (4608)
#define G2_SMEM (4 * BUFW * 4)       // 2 stages x (A|W) = 73,728 B

template<int EPI>
__global__ __launch_bounds__(256)
void gemm2(const __half* __restrict__ A0, const __half* __restrict__ A1,
           const __half* __restrict__ Wq, const __half* __restrict__ Wkv,
           const float* __restrict__ bias0, const float* __restrict__ bias1,
           const float* __restrict__ bias2,
           void* __restrict__ out0, void* __restrict__ out1,
           void* __restrict__ out2, float scale0)
{
    extern __shared__ uint32_t sm2[];
    const int t    = threadIdx.x;
    const int lane = t & 31, wid = t >> 5;
    const int gid  = lane >> 2, tid4 = lane & 3;
    const int wm32 = (wid & 3) * 32;     // warp M offset (4 warps)
    const int wn64 = (wid >> 2) * 64;    // warp N offset (2 warps)
    const int bx   = blockIdx.x;
    const int m0   = blockIdx.y * 128;

    const __half* A;
    const __half* Wb;
    if (EPI == 0) {
        A  = (bx < 8) ? A0 : A1;
        Wb = (bx < 8) ? Wq + (size_t)bx * 128 * D_
                      : Wkv + (size_t)(bx - 8) * 128 * D_;
    } else {
        A  = A0;
        Wb = Wq + (size_t)bx * 128 * D_;
    }
    const uint32_t smb = smem_u32(sm2);

    auto stage = [&](int kc) {
        const uint32_t ab = smb + (uint32_t)(kc & 1) * (2 * BUFW * 4);
        const uint32_t wb = ab + BUFW * 4;
        const int k0 = kc * 64;
        #pragma unroll
        for (int it = 0; it < 4; it++) {
            const int id  = t + it * 256;            // 0..1023
            const int row = id >> 3, ch = id & 7;    // 128 rows x 8 16B-chunks
            const uint32_t off = (uint32_t)(row * RSW + ch * 4) * 4;
            cp16(ab + off, A  + (size_t)(m0 + row) * D_ + k0 + ch * 8);
            cp16(wb + off, Wb + (size_t)row        * D_ + k0 + ch * 8);
        }
    };

    float c[2][8][4];
    #pragma unroll
    for (int rb = 0; rb < 2; rb++)
        #pragma unroll
        for (int j = 0; j < 8; j++)
            #pragma unroll
            for (int i = 0; i < 4; i++) c[rb][j][i] = 0.f;

    stage(0); cp_commit();

    for (int kc = 0; kc < 16; kc++) {
        if (kc + 1 < 16) { stage(kc + 1); cp_commit(); cp_wait<1>(); }
        else             { cp_wait<0>(); }
        __syncthreads();

        const uint32_t* Ab = sm2 + (kc & 1) * 2 * BUFW;
        const uint32_t* Bb = Ab + BUFW;
        #pragma unroll
        for (int ks = 0; ks < 4; ks++) {
            uint32_t a[2][4];
            #pragma unroll
            for (int rb = 0; rb < 2; rb++) {
                const int r0 = wm32 + rb * 16;
                a[rb][0] = Ab[(r0 + gid    ) * RSW + ks * 8 + tid4    ];
                a[rb][1] = Ab[(r0 + gid + 8) * RSW + ks * 8 + tid4    ];
                a[rb][2] = Ab[(r0 + gid    ) * RSW + ks * 8 + tid4 + 4];
                a[rb][3] = Ab[(r0 + gid + 8) * RSW + ks * 8 + tid4 + 4];
            }
            #pragma unroll
            for (int j = 0; j < 8; j++) {
                uint32_t b0 = Bb[(wn64 + j * 8 + gid) * RSW + ks * 8 + tid4    ];
                uint32_t b1 = Bb[(wn64 + j * 8 + gid) * RSW + ks * 8 + tid4 + 4];
                mma_f16(c[0][j], a[0], b0, b1);
                mma_f16(c[1][j], a[1], b0, b1);
            }
        }
        __syncthreads();
    }

    // Epilogue
    if (EPI == 0) {
        __half* outH;
        const float* bs;
        float scale = 1.f;
        int nb;
        if (bx < 8)       { outH = (__half*)out0; bs = bias0; nb = bx * 128;        scale = scale0; }
        else if (bx < 16) { outH = (__half*)out1; bs = bias1; nb = (bx - 8) * 128;  }
        else              { outH = (__half*)out2; bs = bias2; nb = (bx - 16) * 128; }
        #pragma unroll
        for (int rb = 0; rb < 2; rb++) {
            #pragma unroll
            for (int hh = 0; hh < 2; hh++) {
                const int m  = m0 + wm32 + rb * 16 + gid + hh * 8;
                const int bI = m >> 11, s = m & 2047;
                #pragma unroll
                for (int j = 0; j < 8; j++) {
                    const int nf = nb + wn64 + j * 8 + tid4 * 2;
                    const float v0 = c[rb][j][hh * 2 + 0] + bs[nf];
                    const float v1 = c[rb][j][hh * 2 + 1] + bs[nf + 1];
                    const int head = nf >> 6, nl = nf & 63;
                    *(uint32_t*)&outH[(((size_t)(bI * H_ + head)) * SQ_ + s) * HD_ + nl] =
                        packh2(v0 * scale, v1 * scale);
                }
            }
        }
    } else {
        float* out = (float*)out0;
        #pragma unroll
        for (int rb = 0; rb < 2; rb++) {
            #pragma unroll
            for (int hh = 0; hh < 2; hh++) {
                const int m = m0 + wm32 + rb * 16 + gid + hh * 8;
                #pragma unroll
                for (int j = 0; j < 8; j++) {
                    const int nf = bx * 128 + wn64 + j * 8 + tid4 * 2;
                    const float v0 = c[rb][j][hh * 2 + 0] + bias0[nf];
                    const float v1 = c[rb][j][hh * 2 + 1] + bias0[nf + 1];
                    *(float2*)&out[(size_t)m * D_ + nf] = make_float2(v0, v1);
                }
            }
        }
    }
}

// ---------------------------------------------------------------------------
// Flash attention, fp16 mma (byte-identical to the 301us R10 version).
// Block = (b,h,128 q rows), 8 warps, scalar LDS K-frags, x4.trans V.
// ---------------------------------------------------------------------------
__global__ __launch_bounds__(256)
void flash_h()
{
    __shared__ uint32_t pool[9216];   // 36,864 B

    const int t    = threadIdx.x;
    const int lane = t & 31, wid = t >> 5;
    const int gid  = lane >> 2, tid4 = lane & 3;
    const int w16  = wid * 16;

    const int qt = blockIdx.x;
    const int h  = blockIdx.y;
    const int b  = blockIdx.z;

    const size_t qbase  = (((size_t)b * H_ + h) * SQ_ + qt * 128) * HD_;
    const size_t kvbase = (((size_t)b * H_ + h) * SK_) * HD_;

    const uint32_t pb = smem_u32(pool);

    #pragma unroll
    for (int it = 0; it < 4; it++) {
        const int id  = t + it * 256;
        const int row = id >> 3, c8 = (id & 7) * 8;
        cp16(pb + (uint32_t)(row * 36 + (id & 7) * 4) * 4,
             g_Q + qbase + (size_t)row * HD_ + c8);
    }
    cp_commit(); cp_wait<0>();
    __syncthreads();

    uint32_t aQ[4][4];
    #pragma unroll
    for (int ks = 0; ks < 4; ks++) {
        aQ[ks][0] = pool[(w16 + gid    ) * 36 + ks * 8 + tid4    ];
        aQ[ks][1] = pool[(w16 + gid + 8) * 36 + ks * 8 + tid4    ];
        aQ[ks][2] = pool[(w16 + gid    ) * 36 + ks * 8 + tid4 + 4];
        aQ[ks][3] = pool[(w16 + gid + 8) * 36 + ks * 8 + tid4 + 4];
    }
    __syncthreads();

    float cO[8][4];
    #pragma unroll
    for (int j = 0; j < 8; j++)
        #pragma unroll
        for (int i = 0; i < 4; i++) cO[j][i] = 0.f;
    float m0 = -1e30f, m1 = -1e30f, l0 = 0.f, l1 = 0.f;

    auto stageKV = [&](int buf, int c0) {
        #pragma unroll
        for (int it = 0; it < 2; it++) {
            const int id  = t + it * 256;
            const int row = id >> 3, c8 = (id & 7) * 8;
            const size_t go = kvbase + (size_t)(c0 + row) * HD_ + c8;
            cp16(pb + (uint32_t)(       buf * 2304 + row * 36 + (id & 7) * 4) * 4,
                 g_K + go);
            cp16(pb + (uint32_t)(4608 + buf * 2304 + row * 36 + (id & 7) * 4) * 4,
                 g_V + go);
        }
    };

    stageKV(0, 0);
    cp_commit();

    for (int cc = 0; cc < 32; cc++) {
        if (cc + 1 < 32) { stageKV((cc + 1) & 1, (cc + 1) * 64); cp_commit(); cp_wait<1>(); }
        else             { cp_wait<0>(); }
        __syncthreads();

        const uint32_t* Ks = pool + (cc & 1) * 2304;
        const uint32_t  vsb = pb + (uint32_t)(4608 + (cc & 1) * 2304) * 4;

        float cS[8][4];
        #pragma unroll
        for (int j = 0; j < 8; j++)
            #pragma unroll
            for (int i = 0; i < 4; i++) cS[j][i] = 0.f;

        #pragma unroll
        for (int ks = 0; ks < 4; ks++) {
            #pragma unroll
            for (int j = 0; j < 8; j++) {
                uint32_t b0 = Ks[(j * 8 + gid) * 36 + ks * 8 + tid4    ];
                uint32_t b1 = Ks[(j * 8 + gid) * 36 + ks * 8 + tid4 + 4];
                mma_f16(cS[j], aQ[ks], b0, b1);
            }
        }

        float mx0 = -1e30f, mx1 = -1e30f;
        #pragma unroll
        for (int j = 0; j < 8; j++) {
            mx0 = fmaxf(mx0, fmaxf(cS[j][0], cS[j][1]));
            mx1 = fmaxf(mx1, fmaxf(cS[j][2], cS[j][3]));
        }
        mx0 = fmaxf(mx0, __shfl_xor_sync(0xffffffffu, mx0, 1));
        mx0 = fmaxf(mx0, __shfl_xor_sync(0xffffffffu, mx0, 2));
        mx1 = fmaxf(mx1, __shfl_xor_sync(0xffffffffu, mx1, 1));
        mx1 = fmaxf(mx1, __shfl_xor_sync(0xffffffffu, mx1, 2));
        const float nm0 = fmaxf(m0, mx0), nm1 = fmaxf(m1, mx1);
        const float f0 = ex2(m0 - nm0), f1 = ex2(m1 - nm1);
        m0 = nm0; m1 = nm1;

        float s0 = 0.f, s1 = 0.f;
        uint32_t ph[8][2];
        #pragma unroll
        for (int j = 0; j < 8; j++) {
            const float p0 = ex2(cS[j][0] - m0);
            const float p1 = ex2(cS[j][1] - m0);
            const float p2 = ex2(cS[j][2] - m1);
            const float p3 = ex2(cS[j][3] - m1);
            s0 += p0 + p1;  s1 += p2 + p3;
            ph[j][0] = packh2(p0, p1);
            ph[j][1] = packh2(p2, p3);
        }
        s0 += __shfl_xor_sync(0xffffffffu, s0, 1);
        s0 += __shfl_xor_sync(0xffffffffu, s0, 2);
        s1 += __shfl_xor_sync(0xffffffffu, s1, 1);
        s1 += __shfl_xor_sync(0xffffffffu, s1, 2);
        l0 = l0 * f0 + s0;
        l1 = l1 * f1 + s1;

        #pragma unroll
        for (int j = 0; j < 8; j++) {
            cO[j][0] *= f0; cO[j][1] *= f0;
            cO[j][2] *= f1; cO[j][3] *= f1;
        }

        #pragma unroll
        for (int tk = 0; tk < 4; tk++) {
            uint32_t aP[4] = { ph[2*tk][0], ph[2*tk][1],
                               ph[2*tk+1][0], ph[2*tk+1][1] };
            #pragma unroll
            for (int jp = 0; jp < 4; jp++) {
                const int vrow = tk * 16 + (lane & 15);
                const int vcol = (lane >> 4) * 8 + jp * 16;
                uint32_t addr = vsb + (uint32_t)(vrow * 72 + vcol) * 2u;
                uint32_t r0, r1, r2, r3;
                ldmatrix_x4_trans(r0, r1, r2, r3, addr);
                mma_f16(cO[2*jp    ], aP, r0, r1);
                mma_f16(cO[2*jp + 1], aP, r2, r3);
            }
        }
        __syncthreads();
    }

    const float inv0 = 1.f / l0;
    const float inv1 = 1.f / l1;
    const int qrow = qt * 128 + w16 + gid;
    __half* op0 = g_C + ((size_t)(b * SQ_ + qrow)) * D_ + h * HD_;
    __half* op1 = op0 + (size_t)8 * D_;
    #pragma unroll
    for (int j = 0; j < 8; j++) {
        const int nl = j * 8 + tid4 * 2;
        *(uint32_t*)&op0[nl] = packh2(cO[j][0] * inv0, cO[j][1] * inv0);
        *(uint32_t*)&op1[nl] = packh2(cO[j][2] * inv1, cO[j][3] * inv1);
    }
}

// ---------------------------------------------------------------------------
extern "C" void kernel_launch(void* const* d_in, const int* in_sizes, int n_in,
                              void* d_out, int out_size)
{
    const float* x   = (const float*)d_in[0];
    const float* enc = (const float*)d_in[1];
    const float* Wq  = (const float*)d_in[2];
    const float* bq  = (const float*)d_in[3];
    const float* Wk  = (const float*)d_in[4];
    const float* bk  = (const float*)d_in[5];
    const float* Wv  = (const float*)d_in[6];
    const float* bv  = (const float*)d_in[7];
    const float* Wo  = (const float*)d_in[8];
    const float* bo  = (const float*)d_in[9];

    __half *xh, *eh, *Wqh, *Wkvh, *Woh, *Qp, *Kp, *Vp, *Cp;
    cudaGetSymbolAddress((void**)&xh,   g_xh);
    cudaGetSymbolAddress((void**)&eh,   g_eh);
    cudaGetSymbolAddress((void**)&Wqh,  g_Wqh);
    cudaGetSymbolAddress((void**)&Wkvh, g_Wkvh);
    cudaGetSymbolAddress((void**)&Woh,  g_Woh);
    cudaGetSymbolAddress((void**)&Qp,   g_Q);
    cudaGetSymbolAddress((void**)&Kp,   g_K);
    cudaGetSymbolAddress((void**)&Vp,   g_V);
    cudaGetSymbolAddress((void**)&Cp,   g_C);

    // Prepass (fused): activations, QKV weights, Wo
    cvt_f2h2<<<dim3((MTOT*D_/4)/256, 2), 256>>>(x, xh, enc, eh);
    tr_cvt3<<<dim3(HD_/32, D_/32, 3*H_), 256>>>(Wq, Wqh,
                                                Wk, Wkvh,
                                                Wv, Wkvh + (size_t)D_*D_);
    tr_cvt<<<dim3(D_/32, D_/32), 256>>>(Wo, Woh, D_, D_);

    cudaFuncSetAttribute(gemm2<0>, cudaFuncAttributeMaxDynamicSharedMemorySize,
                         G2_SMEM);
    cudaFuncSetAttribute(gemm2<1>, cudaFuncAttributeMaxDynamicSharedMemorySize,
                         G2_SMEM);

    // Merged Q+K+V projections: 24 N-tiles (Q:0-7, K:8-15, V:16-23)
    gemm2<0><<<dim3(24, MTOT/128), 256, G2_SMEM>>>(
        xh, eh, Wqh, Wkvh, bq, bk, bv, Qp, Kp, Vp, QSCALE);

    flash_h<<<dim3(SQ_/128, H_, B_), 256>>>();

    // Output projection: f32 into d_out
    gemm2<1><<<dim3(8, MTOT/128), 256, G2_SMEM>>>(
        Cp, Cp, Woh, Woh, bo, bo, bo, d_out, d_out, d_out, 1.f);
}